// round 17
// baseline (speedup 1.0000x reference)
#include <cuda_runtime.h>
#include <math.h>

// Problem shape (fixed by the reference)
#define B 32
#define S 4096
#define H 768                 // 768 floats = 6 float4 per lane across a warp
#define NROWS (B * S)         // 131072 global rows (hidden is contiguous)
#define GRID 148              // exactly 1 CTA per SM
#define THREADS 512
#define WARPS 16
#define RPC 886               // ceil(131072 / 148) rows per CTA
#define MAXPART (GRID * 2)    // <= 2 partials per CTA (one batch crossing max)

// Scratch (allocation-free). g_count statically zeroed; combiner resets it,
// so every graph replay starts from identical state.
__device__ float g_pm[MAXPART];
__device__ float g_pl[MAXPART];
__device__ float g_pacc[(size_t)MAXPART * H];   // ~910 KB, L2-resident
__device__ unsigned int g_count[B] = {};

// ---------------------------------------------------------------------------
// Fused single-query attention: ONE 512-thread CTA per SM (148 CTAs), the 16
// warps interleave stride-16 rows of the CTA's single contiguous ~2.6 MB
// chunk -> one sequential DRAM window per SM (148 streams chip-wide, was 288).
// Inner loop identical to R16 (best measured). Straddling CTAs (31 of 148)
// process two batch segments and flush a partial per segment.
// ---------------------------------------------------------------------------
__global__ __launch_bounds__(THREADS, 1)
void attn_fused(const float* __restrict__ hidden, const float* __restrict__ q,
                float* __restrict__ out)
{
    const int bx   = blockIdx.x;              // 0..147
    const int wid  = threadIdx.x >> 5;        // 0..15
    const int lane = threadIdx.x & 31;

    __shared__ float s_m[WARPS];
    __shared__ float s_l[WARPS];
    __shared__ float s_acc[8][H];             // 24 KB (two-round merge)
    __shared__ unsigned int s_ticket;

    const float4* qv4 = (const float4*)q;
    float4 qv[6];
#pragma unroll
    for (int i = 0; i < 6; i++) qv[i] = qv4[i * 32 + lane];

    const int g0 = bx * RPC;
    const int g1 = min(g0 + RPC, NROWS);
    const int b0 = g0 >> 12;                  // first batch touched
    const int b1 = (g1 - 1) >> 12;            // last batch touched (b0 or b0+1)

    const int STRIDE4 = (WARPS * H) / 4;      // float4 stride between my rows

    #define LOADROW(buf, pbase, k) do {                                     \
        const float4* rp_ = (pbase) + (size_t)(k) * STRIDE4;                \
        _Pragma("unroll")                                                   \
        for (int i_ = 0; i_ < 6; i_++) buf[i_] = rp_[i_ * 32 + lane];       \
    } while (0)

    #define CONSUME(buf) do {                                               \
        float d0_ = 0.f, d1_ = 0.f;                                         \
        _Pragma("unroll")                                                   \
        for (int i_ = 0; i_ < 3; i_++) {                                    \
            d0_ = fmaf(buf[i_].x, qv[i_].x, d0_);                           \
            d0_ = fmaf(buf[i_].y, qv[i_].y, d0_);                           \
            d0_ = fmaf(buf[i_].z, qv[i_].z, d0_);                           \
            d0_ = fmaf(buf[i_].w, qv[i_].w, d0_);                           \
        }                                                                   \
        _Pragma("unroll")                                                   \
        for (int i_ = 3; i_ < 6; i_++) {                                    \
            d1_ = fmaf(buf[i_].x, qv[i_].x, d1_);                           \
            d1_ = fmaf(buf[i_].y, qv[i_].y, d1_);                           \
            d1_ = fmaf(buf[i_].z, qv[i_].z, d1_);                           \
            d1_ = fmaf(buf[i_].w, qv[i_].w, d1_);                           \
        }                                                                   \
        float d_ = d0_ + d1_;                                               \
        _Pragma("unroll")                                                   \
        for (int o_ = 16; o_ > 0; o_ >>= 1)                                 \
            d_ += __shfl_xor_sync(0xffffffffu, d_, o_);                     \
        if (d_ > m) {                                                       \
            const float sc_ = __expf(m - d_);                               \
            l *= sc_;                                                       \
            _Pragma("unroll")                                               \
            for (int i_ = 0; i_ < 6; i_++) {                                \
                acc[i_].x *= sc_; acc[i_].y *= sc_;                         \
                acc[i_].z *= sc_; acc[i_].w *= sc_;                         \
            }                                                               \
            m = d_;                                                         \
        }                                                                   \
        const float w_ = __expf(d_ - m);                                    \
        l += w_;                                                            \
        _Pragma("unroll")                                                   \
        for (int i_ = 0; i_ < 6; i_++) {                                    \
            acc[i_].x = fmaf(w_, buf[i_].x, acc[i_].x);                     \
            acc[i_].y = fmaf(w_, buf[i_].y, acc[i_].y);                     \
            acc[i_].z = fmaf(w_, buf[i_].z, acc[i_].z);                     \
            acc[i_].w = fmaf(w_, buf[i_].w, acc[i_].w);                     \
        }                                                                   \
    } while (0)

    for (int bb = b0; bb <= b1; bb++) {
        const int r0  = max(g0, bb << 12);
        const int r1  = min(g1, (bb + 1) << 12);
        const int len = r1 - r0;
        const int rem = len - wid;
        const int nrows = rem > 0 ? (rem + WARPS - 1) / WARPS : 0;

        const float4* p = (const float4*)(hidden + (size_t)(r0 + wid) * H);

        float4 acc[6];
#pragma unroll
        for (int i = 0; i < 6; i++) acc[i] = make_float4(0.f, 0.f, 0.f, 0.f);
        float m = -INFINITY;
        float l = 0.f;

        float4 x[6], xn[6];
        if (nrows > 0) LOADROW(x, p, 0);

        int r = 0;
        for (; r + 2 <= nrows; r += 2) {
            LOADROW(xn, p, r + 1);
            CONSUME(x);
            if (r + 2 < nrows) LOADROW(x, p, r + 2);
            CONSUME(xn);
        }
        if (r < nrows) CONSUME(x);

        // ---- two-round CTA merge: 16 warp partials -> one, via 8 smem rows
        if (lane == 0) { s_m[wid] = m; s_l[wid] = l; }
        __syncthreads();

        float M = s_m[0];
#pragma unroll
        for (int w = 1; w < WARPS; w++) M = fmaxf(M, s_m[w]);
        const float myw = __expf(m - M);       // warp-uniform

        // round 1: warps 0-7 write their scaled partial
        if (wid < 8) {
            float4* sa = (float4*)s_acc[wid];
#pragma unroll
            for (int i = 0; i < 6; i++) {
                float4 v = acc[i];
                v.x *= myw; v.y *= myw; v.z *= myw; v.w *= myw;
                sa[i * 32 + lane] = v;
            }
        }
        __syncthreads();
        // round 2: warps 8-15 accumulate their scaled partial on top
        if (wid >= 8) {
            float4* sa = (float4*)s_acc[wid - 8];
#pragma unroll
            for (int i = 0; i < 6; i++) {
                float4 v = sa[i * 32 + lane];
                v.x = fmaf(myw, acc[i].x, v.x);
                v.y = fmaf(myw, acc[i].y, v.y);
                v.z = fmaf(myw, acc[i].z, v.z);
                v.w = fmaf(myw, acc[i].w, v.w);
                sa[i * 32 + lane] = v;
            }
        }
        __syncthreads();

        // flush partial (already scaled by exp(m_w - M)): 512 threads, 768 h
        const int pidx = 2 * bx + (bb - b0);
        float* pa = g_pacc + (size_t)pidx * H;
        {
            const int h = threadIdx.x;         // 0..511
            float rr = 0.f;
#pragma unroll
            for (int w = 0; w < 8; w++) rr += s_acc[w][h];
            pa[h] = rr;
            if (h < H - THREADS) {             // h+512 in [512, 768)
                float r2 = 0.f;
#pragma unroll
                for (int w = 0; w < 8; w++) r2 += s_acc[w][h + THREADS];
                pa[h + THREADS] = r2;
            }
        }
        if (threadIdx.x == 0) {
            float L = 0.f;
#pragma unroll
            for (int w = 0; w < WARPS; w++)
                L = fmaf(__expf(s_m[w] - M), s_l[w], L);
            g_pm[pidx] = M;
            g_pl[pidx] = L;
        }

        // ---- ticket: last flusher for batch bb combines it ----
        const int cf = (bb << 12) / RPC;
        const int cl = min((((bb + 1) << 12) - 1) / RPC, GRID - 1);
        const unsigned cnt = (unsigned)(cl - cf + 1);

        __threadfence();                       // my stores visible chip-wide
        __syncthreads();                       // all threads fenced
        if (threadIdx.x == 0) s_ticket = atomicAdd(&g_count[bb], 1u);
        __syncthreads();

        if (s_ticket == cnt - 1) {
            __threadfence();                   // acquire: see all partials

            float GM = -INFINITY;
            for (int c = cf; c <= cl; c++) {
                const int idx = 2 * c + (((c * RPC) >> 12) != bb ? 1 : 0);
                GM = fmaxf(GM, g_pm[idx]);
            }
            const int h0 = threadIdx.x;        // 0..511
            float ra = 0.f, rb = 0.f, L = 0.f;
            for (int c = cf; c <= cl; c++) {
                const int idx = 2 * c + (((c * RPC) >> 12) != bb ? 1 : 0);
                const float w = __expf(g_pm[idx] - GM);
                const float* pc = g_pacc + (size_t)idx * H;
                L  = fmaf(w, g_pl[idx], L);
                ra = fmaf(w, pc[h0], ra);
                if (h0 < H - THREADS) rb = fmaf(w, pc[h0 + THREADS], rb);
            }
            const float invL = 1.f / L;
            float* ob = out + bb * H;
            ob[h0] = ra * invL;
            if (h0 < H - THREADS) ob[h0 + THREADS] = rb * invL;

            if (threadIdx.x == 0) g_count[bb] = 0;   // reset for next replay
        }
    }
}

extern "C" void kernel_launch(void* const* d_in, const int* in_sizes, int n_in,
                              void* d_out, int out_size)
{
    const float* hidden = (const float*)d_in[0];   // [32, 4096, 768] f32
    const float* querys = (const float*)d_in[1];   // [1, 768] f32
    float* out = (float*)d_out;                    // [32, 768] f32

    attn_fused<<<GRID, THREADS>>>(hidden, querys, out);
}